// round 15
// baseline (speedup 1.0000x reference)
#include <cuda_runtime.h>
#include <cuda_fp16.h>
#include <cstdint>

// ---------------------------------------------------------------------------
// CFModule_12575664243188 on sm_103a (compute_103-safe: no tcgen05):
//   x: [B=16, H=256, W=256, C=64] fp32
//   pooled = adaptive_avg_pool 4x4  -> [B,16,64]
//   dots[b,i,j] = 0.25 * <pooled[:,i], pooled[:,j]>; attn = softmax_j
//   out[b,s,t] = gelu( sum_c x[b,s,c] * attn[b,t,c] )
//
// pool (1024 blocks) -> attn (16 blocks) -> gemm.
// gemm: TILE_S=128, 8 warps as 4(M)x2(N); attn tile via cp.async.ca;
// x load/convert/store fused per-iteration under __launch_bounds__(256,5)
// so ptxas fits 5 CTAs/SM (reg cap 51) without spilling the whole tile;
// fp16 mma.sync fp32-accum; tanh.approx GELU; 32KB block-wide smem stage
// -> coalesced STG.128 evict-first.
// ---------------------------------------------------------------------------

#define B_    16
#define Hc    256
#define Wc    256
#define Cc    64
#define HW    (Hc*Wc)          // 65536
#define TILE_S 128

// --------------------------- global scratch --------------------------------
__device__ float g_pp[1024 * 64];                    // pool partials [b][n][q][c]
__device__ uint4 g_attn_h4[B_ * 512];                // attn fp16 [b][t][c]

// --------------------------- helpers ---------------------------------------
__device__ __forceinline__ uint32_t smem_u32(const void* p) {
    uint32_t a;
    asm("{ .reg .u64 t; cvta.to.shared.u64 t, %1; cvt.u32.u64 %0, t; }"
        : "=r"(a) : "l"(p));
    return a;
}

#define CP_ASYNC_CA16(dst, src) \
    asm volatile("cp.async.ca.shared.global [%0], [%1], 16;" \
                 :: "r"(dst), "l"(src) : "memory")
#define CP_COMMIT() asm volatile("cp.async.commit_group;" ::: "memory")
#define CP_WAIT0()  asm volatile("cp.async.wait_group 0;" ::: "memory")

__device__ __forceinline__ void ldsm_x4(uint32_t& r0, uint32_t& r1,
                                        uint32_t& r2, uint32_t& r3, uint32_t addr) {
    asm volatile("ldmatrix.sync.aligned.m8n8.x4.shared.b16 {%0,%1,%2,%3}, [%4];"
                 : "=r"(r0), "=r"(r1), "=r"(r2), "=r"(r3) : "r"(addr));
}

__device__ __forceinline__ void mma_f16(float* c, uint32_t a0, uint32_t a1,
                                        uint32_t a2, uint32_t a3,
                                        uint32_t b0, uint32_t b1) {
    asm volatile(
        "mma.sync.aligned.m16n8k16.row.col.f32.f16.f16.f32 "
        "{%0,%1,%2,%3}, {%4,%5,%6,%7}, {%8,%9}, {%0,%1,%2,%3};"
        : "+f"(c[0]), "+f"(c[1]), "+f"(c[2]), "+f"(c[3])
        : "r"(a0), "r"(a1), "r"(a2), "r"(a3), "r"(b0), "r"(b1));
}

// GELU via HW tanh: 0.5*v*(1 + tanh(0.79788456*(v + 0.044715 v^3)))
__device__ __forceinline__ float gelu_fast(float v) {
    float v2 = v * v;
    float p = fmaf(0.0356774081f, v2, 0.7978845608f);
    float arg = p * v;
    float t;
    asm("tanh.approx.f32 %0, %1;" : "=f"(t) : "f"(arg));
    float h = 0.5f * v;
    return fmaf(h, t, h);
}

// ---------------------------------------------------------------------------
// Kernel A: pool partials. grid = 1024 (b*64 + n*4 + q), 256 threads.
// ---------------------------------------------------------------------------
__global__ void __launch_bounds__(256) pool_kernel(const float* __restrict__ x)
{
    int blk = blockIdx.x;
    int q = blk & 3, n = (blk >> 2) & 15, b = blk >> 6;
    int ph = n >> 2, pw = n & 3;
    int tid = threadIdx.x;

    float4 acc = make_float4(0.f, 0.f, 0.f, 0.f);
    for (int hh = 0; hh < 16; ++hh) {
        int h = ph * 64 + q * 16 + hh;
        const float4* row = (const float4*)(
            x + (((size_t)b * Hc + h) * Wc + (size_t)pw * 64) * Cc);
        #pragma unroll
        for (int it = 0; it < 4; ++it) {
            float4 v = row[tid + 256 * it];
            acc.x += v.x; acc.y += v.y; acc.z += v.z; acc.w += v.w;
        }
    }
    __shared__ float4 sm[256];
    sm[tid] = acc;
    __syncthreads();
    if (tid < 64) {
        int r = tid >> 2, j = tid & 3;
        float s = 0.f;
        #pragma unroll
        for (int w = 0; w < 16; ++w)
            s += ((const float*)&sm[r + 16 * w])[j];
        g_pp[blk * 64 + tid] = s;
    }
}

// ---------------------------------------------------------------------------
// Kernel B: merge partials, gram + softmax, emit fp16 attn. grid = B_.
// ---------------------------------------------------------------------------
__global__ void __launch_bounds__(64) attn_kernel()
{
    int b = blockIdx.x;
    int i = threadIdx.x;
    __shared__ float xs[64][17];
    float my[16];
    #pragma unroll
    for (int n = 0; n < 16; ++n) {
        int base = ((b * 16 + n) * 4) * 64 + i;
        float v = (g_pp[base] + g_pp[base + 64] + g_pp[base + 128] + g_pp[base + 192])
                  * (1.0f / 4096.0f);
        xs[i][n] = v;
        my[n] = v;
    }
    __syncthreads();

    float d[64];
    float mx = -1e30f;
    #pragma unroll
    for (int j = 0; j < 64; ++j) {
        float s = 0.f;
        #pragma unroll
        for (int n = 0; n < 16; ++n) s += my[n] * xs[j][n];
        s *= 0.25f;
        d[j] = s;
        mx = fmaxf(mx, s);
    }
    float sum = 0.f;
    #pragma unroll
    for (int j = 0; j < 64; ++j) { d[j] = expf(d[j] - mx); sum += d[j]; }
    float inv = 1.0f / sum;

    __half* ah = (__half*)g_attn_h4;
    size_t rb = ((size_t)b * 64 + i) * 64;
    #pragma unroll
    for (int j = 0; j < 64; ++j)
        ah[rb + j] = __float2half_rn(d[j] * inv);
}

// ---------------------------------------------------------------------------
// Kernel C: fp16 mma.sync GEMM + fast GELU. grid = (HW/128, B), 8 warps.
// Warp grid 4(M) x 2(N): warp (wm, wn) owns rows [wm*32, wm*32+32),
// cols [wn*32, wn*32+32).
// SMEM (static 32KB): BH [64][64] f16 (8KB) @0, XH [128][64] f16 (16KB) @8192;
// after mainloop the full 32KB is a fp32 stage tile [128][64] (256B rows).
// __launch_bounds__(256, 5): reg cap 51 -> 5 CTAs/SM; the fused
// load/convert/store loop lets ptxas front-batch as many LDGs as fit.
// ---------------------------------------------------------------------------
#define OFF_BH 0
#define OFF_XH 8192

__global__ void __launch_bounds__(256, 5) gemm_kernel(const float* __restrict__ x,
                                                      float* __restrict__ out)
{
    __shared__ __align__(128) unsigned char smem[32768];
    uint32_t sb = smem_u32(smem);
    int tid = threadIdx.x;
    int wid = tid >> 5, lid = tid & 31;
    int wm = wid & 3, wn = wid >> 2;
    int b = blockIdx.y;
    int s0 = blockIdx.x * TILE_S;

    // ---- attn tile via cp.async.ca (L1-kept; shared across CTAs on an SM)
    const uint4* gh = g_attn_h4 + (size_t)b * 512;
    #pragma unroll
    for (int it = 0; it < 2; ++it) {
        int m = tid + 256 * it;               // uint4 index (512 total)
        int row = m >> 3;
        uint32_t off = row * 128 + (((uint32_t)(m & 7) * 16) ^ ((row & 7) << 4));
        CP_ASYNC_CA16(sb + OFF_BH + off, gh + m);
    }
    CP_COMMIT();

    // ---- x tile: fused load -> fp16 convert -> swizzled STS (ptxas
    //      front-batches LDGs up to the register cap)
    const float4* gx = (const float4*)(x + ((size_t)b * HW + s0) * Cc);
    #pragma unroll
    for (int it = 0; it < 8; ++it) {
        int f = tid + 256 * it;               // float4 index (2048 total)
        float4 v = __ldcs(&gx[f]);
        __half2 h0 = __float22half2_rn(make_float2(v.x, v.y));
        __half2 h1 = __float22half2_rn(make_float2(v.z, v.w));
        int row = f >> 4;
        uint32_t off = row * 128 + (((uint32_t)(f & 15) * 8) ^ ((row & 7) << 4));
        *(uint2*)(smem + OFF_XH + off) =
            make_uint2(*(uint32_t*)&h0, *(uint32_t*)&h1);
    }
    CP_WAIT0();
    __syncthreads();

    // ---- MMA mainloop: acc[mi][j], j = ntp*2 + half (32 HMMA / warp)
    float acc[2][4][4];
    #pragma unroll
    for (int mi = 0; mi < 2; ++mi)
        #pragma unroll
        for (int j = 0; j < 4; ++j)
            #pragma unroll
            for (int k = 0; k < 4; ++k) acc[mi][j][k] = 0.f;

    uint32_t a_lane = lid & 15;
    uint32_t a_k16 = (lid >> 4) & 1;
    uint32_t b_nrow_lo = (lid & 7) + ((lid >> 4) & 1) * 8;
    uint32_t b_k16 = (lid >> 3) & 1;

    #pragma unroll
    for (int kc = 0; kc < 4; ++kc) {
        uint32_t kb = kc * 32;
        uint32_t Bf[2][4];
        #pragma unroll
        for (int ntp = 0; ntp < 2; ++ntp) {
            uint32_t bn = wn * 32 + ntp * 16 + b_nrow_lo;
            uint32_t b_off = bn * 128 + ((kb + b_k16 * 16) ^ ((bn & 7) << 4));
            ldsm_x4(Bf[ntp][0], Bf[ntp][1], Bf[ntp][2], Bf[ntp][3],
                    sb + OFF_BH + b_off);
        }
        #pragma unroll
        for (int mi = 0; mi < 2; ++mi) {
            uint32_t a_row = wm * 32 + mi * 16 + a_lane;
            uint32_t a_off = a_row * 128 + ((kb + a_k16 * 16) ^ ((a_row & 7) << 4));
            uint32_t A0, A1, A2, A3;
            ldsm_x4(A0, A1, A2, A3, sb + OFF_XH + a_off);
            mma_f16(acc[mi][0], A0, A1, A2, A3, Bf[0][0], Bf[0][1]);
            mma_f16(acc[mi][1], A0, A1, A2, A3, Bf[0][2], Bf[0][3]);
            mma_f16(acc[mi][2], A0, A1, A2, A3, Bf[1][0], Bf[1][1]);
            mma_f16(acc[mi][3], A0, A1, A2, A3, Bf[1][2], Bf[1][3]);
        }
    }

    // tiles fully consumed; reuse ALL smem as a [128][64] fp32 stage
    __syncthreads();

    // ---- stage GELU'd output: row r at r*256, 16B chunks XOR (r&7)<<4
    {
        int rl = lid >> 2;
        uint32_t cb = (uint32_t)(lid & 3) * 8;
        #pragma unroll
        for (int mi = 0; mi < 2; ++mi) {
            #pragma unroll
            for (int j = 0; j < 4; ++j) {
                uint32_t byteoff = wn * 128 + (j >> 1) * 64 + (j & 1) * 32 + cb;
                int r0 = wm * 32 + mi * 16 + rl;
                int r1 = r0 + 8;
                float2 v0, v1;
                v0.x = gelu_fast(acc[mi][j][0]);
                v0.y = gelu_fast(acc[mi][j][1]);
                v1.x = gelu_fast(acc[mi][j][2]);
                v1.y = gelu_fast(acc[mi][j][3]);
                uint32_t o0 = r0 * 256 + (byteoff ^ (((uint32_t)(r0 & 7)) << 4));
                uint32_t o1 = r1 * 256 + (byteoff ^ (((uint32_t)(r1 & 7)) << 4));
                *(float2*)(smem + o0) = v0;
                *(float2*)(smem + o1) = v1;
            }
        }
    }
    __syncthreads();

    // ---- coalesced STG.128 (evict-first: out never re-read)
    float* ob = out + ((size_t)b * HW + s0) * Cc;
    #pragma unroll
    for (int it = 0; it < 8; ++it) {
        int idx = tid + 256 * it;             // uint4 index (2048 total)
        int r = idx >> 4;
        uint32_t chunk = ((uint32_t)(idx & 15) * 16) ^ (((uint32_t)(r & 7)) << 4);
        uint4 d = *(uint4*)(smem + r * 256 + chunk);
        __stcs((uint4*)((char*)ob + (size_t)idx * 16), d);
    }
}

// ---------------------------------------------------------------------------
extern "C" void kernel_launch(void* const* d_in, const int* in_sizes, int n_in,
                              void* d_out, int out_size)
{
    const float* x = (const float*)d_in[0];
    float* out = (float*)d_out;
    (void)in_sizes; (void)n_in; (void)out_size;

    pool_kernel<<<1024, 256>>>(x);
    attn_kernel<<<B_, 64>>>();
    gemm_kernel<<<dim3(HW / TILE_S, B_), 256>>>(x, out);
}

// round 16
// speedup vs baseline: 1.0890x; 1.0890x over previous
#include <cuda_runtime.h>
#include <cuda_fp16.h>
#include <cstdint>

// ---------------------------------------------------------------------------
// CFModule_12575664243188 on sm_103a (compute_103-safe: no tcgen05):
//   x: [B=16, H=256, W=256, C=64] fp32
//   pooled = adaptive_avg_pool 4x4  -> [B,16,64]
//   dots[b,i,j] = 0.25 * <pooled[:,i], pooled[:,j]>; attn = softmax_j
//   out[b,s,t] = gelu( sum_c x[b,s,c] * attn[b,t,c] )
//
// FINAL (= best measured config, R14, 137.7us):
//   pool (1024 blocks, ~80% DRAM) -> attn (16 blocks) -> gemm.
//   gemm: TILE_S=128, 8 warps as 4(M)x2(N); attn tile via cp.async.ca;
//   x tile: 8 front-batched LDG.128 (__ldcs) -> in-reg fp16 convert ->
//   swizzled STS; fp16 mma.sync fp32-accum; tanh.approx GELU; 32KB
//   block-wide smem stage -> coalesced STG.128 evict-first. 4 CTAs/SM.
// ---------------------------------------------------------------------------

#define B_    16
#define Hc    256
#define Wc    256
#define Cc    64
#define HW    (Hc*Wc)          // 65536
#define TILE_S 128

// --------------------------- global scratch --------------------------------
__device__ float g_pp[1024 * 64];                    // pool partials [b][n][q][c]
__device__ uint4 g_attn_h4[B_ * 512];                // attn fp16 [b][t][c]

// --------------------------- helpers ---------------------------------------
__device__ __forceinline__ uint32_t smem_u32(const void* p) {
    uint32_t a;
    asm("{ .reg .u64 t; cvta.to.shared.u64 t, %1; cvt.u32.u64 %0, t; }"
        : "=r"(a) : "l"(p));
    return a;
}

#define CP_ASYNC_CA16(dst, src) \
    asm volatile("cp.async.ca.shared.global [%0], [%1], 16;" \
                 :: "r"(dst), "l"(src) : "memory")
#define CP_COMMIT() asm volatile("cp.async.commit_group;" ::: "memory")
#define CP_WAIT0()  asm volatile("cp.async.wait_group 0;" ::: "memory")

__device__ __forceinline__ void ldsm_x4(uint32_t& r0, uint32_t& r1,
                                        uint32_t& r2, uint32_t& r3, uint32_t addr) {
    asm volatile("ldmatrix.sync.aligned.m8n8.x4.shared.b16 {%0,%1,%2,%3}, [%4];"
                 : "=r"(r0), "=r"(r1), "=r"(r2), "=r"(r3) : "r"(addr));
}

__device__ __forceinline__ void mma_f16(float* c, uint32_t a0, uint32_t a1,
                                        uint32_t a2, uint32_t a3,
                                        uint32_t b0, uint32_t b1) {
    asm volatile(
        "mma.sync.aligned.m16n8k16.row.col.f32.f16.f16.f32 "
        "{%0,%1,%2,%3}, {%4,%5,%6,%7}, {%8,%9}, {%0,%1,%2,%3};"
        : "+f"(c[0]), "+f"(c[1]), "+f"(c[2]), "+f"(c[3])
        : "r"(a0), "r"(a1), "r"(a2), "r"(a3), "r"(b0), "r"(b1));
}

// GELU via HW tanh: 0.5*v*(1 + tanh(0.79788456*(v + 0.044715 v^3)))
__device__ __forceinline__ float gelu_fast(float v) {
    float v2 = v * v;
    float p = fmaf(0.0356774081f, v2, 0.7978845608f);
    float arg = p * v;
    float t;
    asm("tanh.approx.f32 %0, %1;" : "=f"(t) : "f"(arg));
    float h = 0.5f * v;
    return fmaf(h, t, h);
}

// ---------------------------------------------------------------------------
// Kernel A: pool partials. grid = 1024 (b*64 + n*4 + q), 256 threads.
// ---------------------------------------------------------------------------
__global__ void __launch_bounds__(256) pool_kernel(const float* __restrict__ x)
{
    int blk = blockIdx.x;
    int q = blk & 3, n = (blk >> 2) & 15, b = blk >> 6;
    int ph = n >> 2, pw = n & 3;
    int tid = threadIdx.x;

    float4 acc = make_float4(0.f, 0.f, 0.f, 0.f);
    for (int hh = 0; hh < 16; ++hh) {
        int h = ph * 64 + q * 16 + hh;
        const float4* row = (const float4*)(
            x + (((size_t)b * Hc + h) * Wc + (size_t)pw * 64) * Cc);
        #pragma unroll
        for (int it = 0; it < 4; ++it) {
            float4 v = row[tid + 256 * it];
            acc.x += v.x; acc.y += v.y; acc.z += v.z; acc.w += v.w;
        }
    }
    __shared__ float4 sm[256];
    sm[tid] = acc;
    __syncthreads();
    if (tid < 64) {
        int r = tid >> 2, j = tid & 3;
        float s = 0.f;
        #pragma unroll
        for (int w = 0; w < 16; ++w)
            s += ((const float*)&sm[r + 16 * w])[j];
        g_pp[blk * 64 + tid] = s;
    }
}

// ---------------------------------------------------------------------------
// Kernel B: merge partials, gram + softmax, emit fp16 attn. grid = B_.
// ---------------------------------------------------------------------------
__global__ void __launch_bounds__(64) attn_kernel()
{
    int b = blockIdx.x;
    int i = threadIdx.x;
    __shared__ float xs[64][17];
    float my[16];
    #pragma unroll
    for (int n = 0; n < 16; ++n) {
        int base = ((b * 16 + n) * 4) * 64 + i;
        float v = (g_pp[base] + g_pp[base + 64] + g_pp[base + 128] + g_pp[base + 192])
                  * (1.0f / 4096.0f);
        xs[i][n] = v;
        my[n] = v;
    }
    __syncthreads();

    float d[64];
    float mx = -1e30f;
    #pragma unroll
    for (int j = 0; j < 64; ++j) {
        float s = 0.f;
        #pragma unroll
        for (int n = 0; n < 16; ++n) s += my[n] * xs[j][n];
        s *= 0.25f;
        d[j] = s;
        mx = fmaxf(mx, s);
    }
    float sum = 0.f;
    #pragma unroll
    for (int j = 0; j < 64; ++j) { d[j] = expf(d[j] - mx); sum += d[j]; }
    float inv = 1.0f / sum;

    __half* ah = (__half*)g_attn_h4;
    size_t rb = ((size_t)b * 64 + i) * 64;
    #pragma unroll
    for (int j = 0; j < 64; ++j)
        ah[rb + j] = __float2half_rn(d[j] * inv);
}

// ---------------------------------------------------------------------------
// Kernel C: fp16 mma.sync GEMM + fast GELU. grid = (HW/128, B), 8 warps.
// Warp grid 4(M) x 2(N): warp (wm, wn) owns rows [wm*32, wm*32+32),
// cols [wn*32, wn*32+32).
// SMEM (static 32KB): BH [64][64] f16 (8KB) @0, XH [128][64] f16 (16KB) @8192;
// after mainloop the full 32KB is a fp32 stage tile [128][64] (256B rows).
// ---------------------------------------------------------------------------
#define OFF_BH 0
#define OFF_XH 8192

__global__ void __launch_bounds__(256, 4) gemm_kernel(const float* __restrict__ x,
                                                      float* __restrict__ out)
{
    __shared__ __align__(128) unsigned char smem[32768];
    uint32_t sb = smem_u32(smem);
    int tid = threadIdx.x;
    int wid = tid >> 5, lid = tid & 31;
    int wm = wid & 3, wn = wid >> 2;
    int b = blockIdx.y;
    int s0 = blockIdx.x * TILE_S;

    // ---- attn tile via cp.async.ca (L1-kept; shared across CTAs on an SM)
    const uint4* gh = g_attn_h4 + (size_t)b * 512;
    #pragma unroll
    for (int it = 0; it < 2; ++it) {
        int m = tid + 256 * it;               // uint4 index (512 total)
        int row = m >> 3;
        uint32_t off = row * 128 + (((uint32_t)(m & 7) * 16) ^ ((row & 7) << 4));
        CP_ASYNC_CA16(sb + OFF_BH + off, gh + m);
    }
    CP_COMMIT();

    // ---- x tile: 8 front-batched streaming loads, convert in regs
    const float4* gx = (const float4*)(x + ((size_t)b * HW + s0) * Cc);
    float4 v[8];
    #pragma unroll
    for (int it = 0; it < 8; ++it) v[it] = __ldcs(&gx[tid + 256 * it]);

    #pragma unroll
    for (int it = 0; it < 8; ++it) {
        int f = tid + 256 * it;               // float4 index (2048 total)
        __half2 h0 = __float22half2_rn(make_float2(v[it].x, v[it].y));
        __half2 h1 = __float22half2_rn(make_float2(v[it].z, v[it].w));
        int row = f >> 4;
        uint32_t off = row * 128 + (((uint32_t)(f & 15) * 8) ^ ((row & 7) << 4));
        *(uint2*)(smem + OFF_XH + off) =
            make_uint2(*(uint32_t*)&h0, *(uint32_t*)&h1);
    }
    CP_WAIT0();
    __syncthreads();

    // ---- MMA mainloop: acc[mi][j], j = ntp*2 + half (32 HMMA / warp)
    float acc[2][4][4];
    #pragma unroll
    for (int mi = 0; mi < 2; ++mi)
        #pragma unroll
        for (int j = 0; j < 4; ++j)
            #pragma unroll
            for (int k = 0; k < 4; ++k) acc[mi][j][k] = 0.f;

    uint32_t a_lane = lid & 15;
    uint32_t a_k16 = (lid >> 4) & 1;
    uint32_t b_nrow_lo = (lid & 7) + ((lid >> 4) & 1) * 8;
    uint32_t b_k16 = (lid >> 3) & 1;

    #pragma unroll
    for (int kc = 0; kc < 4; ++kc) {
        uint32_t kb = kc * 32;
        uint32_t Bf[2][4];
        #pragma unroll
        for (int ntp = 0; ntp < 2; ++ntp) {
            uint32_t bn = wn * 32 + ntp * 16 + b_nrow_lo;
            uint32_t b_off = bn * 128 + ((kb + b_k16 * 16) ^ ((bn & 7) << 4));
            ldsm_x4(Bf[ntp][0], Bf[ntp][1], Bf[ntp][2], Bf[ntp][3],
                    sb + OFF_BH + b_off);
        }
        #pragma unroll
        for (int mi = 0; mi < 2; ++mi) {
            uint32_t a_row = wm * 32 + mi * 16 + a_lane;
            uint32_t a_off = a_row * 128 + ((kb + a_k16 * 16) ^ ((a_row & 7) << 4));
            uint32_t A0, A1, A2, A3;
            ldsm_x4(A0, A1, A2, A3, sb + OFF_XH + a_off);
            mma_f16(acc[mi][0], A0, A1, A2, A3, Bf[0][0], Bf[0][1]);
            mma_f16(acc[mi][1], A0, A1, A2, A3, Bf[0][2], Bf[0][3]);
            mma_f16(acc[mi][2], A0, A1, A2, A3, Bf[1][0], Bf[1][1]);
            mma_f16(acc[mi][3], A0, A1, A2, A3, Bf[1][2], Bf[1][3]);
        }
    }

    // tiles fully consumed; reuse ALL smem as a [128][64] fp32 stage
    __syncthreads();

    // ---- stage GELU'd output: row r at r*256, 16B chunks XOR (r&7)<<4
    {
        int rl = lid >> 2;
        uint32_t cb = (uint32_t)(lid & 3) * 8;
        #pragma unroll
        for (int mi = 0; mi < 2; ++mi) {
            #pragma unroll
            for (int j = 0; j < 4; ++j) {
                uint32_t byteoff = wn * 128 + (j >> 1) * 64 + (j & 1) * 32 + cb;
                int r0 = wm * 32 + mi * 16 + rl;
                int r1 = r0 + 8;
                float2 v0, v1;
                v0.x = gelu_fast(acc[mi][j][0]);
                v0.y = gelu_fast(acc[mi][j][1]);
                v1.x = gelu_fast(acc[mi][j][2]);
                v1.y = gelu_fast(acc[mi][j][3]);
                uint32_t o0 = r0 * 256 + (byteoff ^ (((uint32_t)(r0 & 7)) << 4));
                uint32_t o1 = r1 * 256 + (byteoff ^ (((uint32_t)(r1 & 7)) << 4));
                *(float2*)(smem + o0) = v0;
                *(float2*)(smem + o1) = v1;
            }
        }
    }
    __syncthreads();

    // ---- coalesced STG.128 (evict-first: out never re-read)
    float* ob = out + ((size_t)b * HW + s0) * Cc;
    #pragma unroll
    for (int it = 0; it < 8; ++it) {
        int idx = tid + 256 * it;             // uint4 index (2048 total)
        int r = idx >> 4;
        uint32_t chunk = ((uint32_t)(idx & 15) * 16) ^ (((uint32_t)(r & 7)) << 4);
        uint4 d = *(uint4*)(smem + r * 256 + chunk);
        __stcs((uint4*)((char*)ob + (size_t)idx * 16), d);
    }
}

// ---------------------------------------------------------------------------
extern "C" void kernel_launch(void* const* d_in, const int* in_sizes, int n_in,
                              void* d_out, int out_size)
{
    const float* x = (const float*)d_in[0];
    float* out = (float*)d_out;
    (void)in_sizes; (void)n_in; (void)out_size;

    pool_kernel<<<1024, 256>>>(x);
    attn_kernel<<<B_, 64>>>();
    gemm_kernel<<<dim3(HW / TILE_S, B_), 256>>>(x, out);
}